// round 4
// baseline (speedup 1.0000x reference)
#include <cuda_runtime.h>
#include <cuda_bf16.h>
#include <cstdint>

#define B_ 8
#define P_ 64
#define S_ 256
#define D_ 256

// ---------------- device scratch (zero-init at load; reset each run) ----------------
__device__ float g_partials[P_ * 16 * 5];
__device__ float g_scale[P_];
__device__ float g_bias[P_];
__device__ int   g_cnt[P_];
__device__ int   g_cnt2[P_];
__device__ int   g_flag[P_];

__device__ __forceinline__ uint32_t smem_to_u32(const void* p) {
    uint32_t a;
    asm("{ .reg .u64 t; cvta.to.shared.u64 t, %1; cvt.u32.u64 %0, t; }" : "=r"(a) : "l"(p));
    return a;
}

#define LDSM4(d0, d1, d2, d3, a) \
    asm volatile("ldmatrix.sync.aligned.m8n8.x4.shared.b16 {%0,%1,%2,%3}, [%4];" \
                 : "=r"(d0), "=r"(d1), "=r"(d2), "=r"(d3) : "r"(a))

#define HMMA(c, a0, a1, a2, a3, b0, b1) \
    asm volatile("mma.sync.aligned.m16n8k16.row.col.f32.bf16.bf16.f32 " \
                 "{%0,%1,%2,%3}, {%4,%5,%6,%7}, {%8,%9}, {%0,%1,%2,%3};" \
                 : "+f"((c)[0]), "+f"((c)[1]), "+f"((c)[2]), "+f"((c)[3]) \
                 : "r"(a0), "r"(a1), "r"(a2), "r"(a3), "r"(b0), "r"(b1))

// ---------------- smem layout (bytes) ----------------
constexpr int ROWB      = 144;                       // 64 k-elems *2B + 16B pad (conflict-free ldmatrix)
constexpr int OFF_XS    = 0;                         // fp32 x rows [s0,s0+128): 128*1024 = 131072
constexpr int OFF_BH    = 131072;                    // hi bf16 chunk: 256*144 = 36864
constexpr int OFF_BL    = OFF_BH + 36864;            // lo bf16 chunk
constexpr int SMEM_BYTES = OFF_BL + 36864;           // 204800
// reuse of the BH/BL region after the last mma:
constexpr int OFF_REDP  = OFF_BH;                    // 128*17*4 = 8704
constexpr int OFF_RS    = OFF_REDP + 8704;           // 512
constexpr int OFF_S2    = OFF_RS + 512;              // 512
constexpr int OFF_RED   = OFF_S2 + 512;              // 512
constexpr int OFF_W8    = OFF_RED + 512;             // 32
constexpr int OFF_BC    = OFF_W8 + 32;               // 8

// =====================================================================
__global__ void __launch_bounds__(256, 1)
da_fused_kernel(const float* __restrict__ x, const float* __restrict__ w,
                const float* __restrict__ gamma, const float* __restrict__ beta,
                float* __restrict__ out)
{
    extern __shared__ __align__(16) char sm[];
    const uint32_t smb = smem_to_u32(sm);
    const int tid = threadIdx.x, wid = tid >> 5, lane = tid & 31;
    const int bx = blockIdx.x;                 // 0..15 = b*2 + st
    const int b = bx >> 1, st = bx & 1;
    const int p = blockIdx.y;
    const int s0 = st * 128;
    const float* xbp = x + (size_t)(b * P_ + p) * (S_ * D_);

    const int warp_m = wid >> 2;   // 0..1 : 64 m-rows
    const int warp_n = wid & 3;    // 0..3 : 64 n-cols

    // accumulators: 4 m-frags x 8 n-frags x 4 f32
    float acc[4][8][4];
    #pragma unroll
    for (int mi = 0; mi < 4; ++mi)
        #pragma unroll
        for (int nf = 0; nf < 8; ++nf)
            #pragma unroll
            for (int q = 0; q < 4; ++q) acc[mi][nf][q] = 0.f;

    // ldmatrix per-lane addressing (identical pattern for A and B operands)
    const uint32_t lrow = lane & 15;
    const uint32_t lcol = (lane >> 4) * 16;    // bytes: k-half select
    uint32_t aaddr[4], baddr[4];
    #pragma unroll
    for (int mi = 0; mi < 4; ++mi)
        aaddr[mi] = smb + OFF_BH + (uint32_t)(s0 + warp_m * 64 + mi * 16 + lrow) * ROWB + lcol;
    #pragma unroll
    for (int nj = 0; nj < 4; ++nj)
        baddr[nj] = smb + OFF_BH + (uint32_t)(warp_n * 64 + nj * 16 + lrow) * ROWB + lcol;

    const int rbase = tid >> 4;    // 0..15
    const int c4    = tid & 15;    // float4 col in 64-k chunk

    // ---- prefetch registers: full 64-col chunk slice per thread (16 float4) ----
    float4 pf[16];
    {
        const float* xc = xbp + c4 * 4;        // chunk 0
        #pragma unroll
        for (int j = 0; j < 16; ++j)
            pf[j] = __ldg(reinterpret_cast<const float4*>(xc + (size_t)(rbase + 16 * j) * D_));
    }

    // ================= k-chunk loop: cvt/STS (prefetched) + MMA w/ next-chunk LDG =================
    for (int kc = 0; kc < 4; ++kc) {
        // ---- convert prefetched chunk kc into hi/lo smem (+ xsave) ----
        #pragma unroll
        for (int j = 0; j < 16; ++j) {
            int row = rbase + 16 * j;
            float4 v = pf[j];
            __nv_bfloat162 h01 = __floats2bfloat162_rn(v.x, v.y);
            __nv_bfloat162 h23 = __floats2bfloat162_rn(v.z, v.w);
            __nv_bfloat162 l01 = __floats2bfloat162_rn(v.x - __low2float(h01),
                                                       v.y - __high2float(h01));
            __nv_bfloat162 l23 = __floats2bfloat162_rn(v.z - __low2float(h23),
                                                       v.w - __high2float(h23));
            uint32_t off = (uint32_t)row * ROWB + (uint32_t)c4 * 8;
            *reinterpret_cast<uint2*>(sm + OFF_BH + off) =
                make_uint2(*reinterpret_cast<uint32_t*>(&h01), *reinterpret_cast<uint32_t*>(&h23));
            *reinterpret_cast<uint2*>(sm + OFF_BL + off) =
                make_uint2(*reinterpret_cast<uint32_t*>(&l01), *reinterpret_cast<uint32_t*>(&l23));
            int rl = row - s0;
            if (rl >= 0 && rl < 128)
                *reinterpret_cast<float4*>(sm + OFF_XS + (size_t)rl * 1024 + kc * 256 + c4 * 16) = v;
        }
        __syncthreads();

        const float* xn = xbp + (kc + 1) * 64 + c4 * 4;   // next chunk base (guarded below)
        #pragma unroll
        for (int ks = 0; ks < 4; ++ks) {
            // ---- interleave next-chunk global loads behind HMMA issue ----
            if (kc < 3 && ks == 0) {
                #pragma unroll
                for (int j = 0; j < 8; ++j)
                    pf[j] = __ldg(reinterpret_cast<const float4*>(xn + (size_t)(rbase + 16 * j) * D_));
            }
            if (kc < 3 && ks == 2) {
                #pragma unroll
                for (int j = 8; j < 16; ++j)
                    pf[j] = __ldg(reinterpret_cast<const float4*>(xn + (size_t)(rbase + 16 * j) * D_));
            }

            const uint32_t ko = (uint32_t)ks * 32;
            uint32_t ah[4][4], al[4][4], bb[4][4];
            #pragma unroll
            for (int mi = 0; mi < 4; ++mi) {
                LDSM4(ah[mi][0], ah[mi][1], ah[mi][2], ah[mi][3], aaddr[mi] + ko);
                LDSM4(al[mi][0], al[mi][1], al[mi][2], al[mi][3], aaddr[mi] + ko + 36864u);
            }
            #pragma unroll
            for (int nj = 0; nj < 4; ++nj)
                LDSM4(bb[nj][0], bb[nj][1], bb[nj][2], bb[nj][3], baddr[nj] + ko);
            // hi*hi and lo*hi
            #pragma unroll
            for (int mi = 0; mi < 4; ++mi)
                #pragma unroll
                for (int nf = 0; nf < 8; ++nf) {
                    HMMA(acc[mi][nf], ah[mi][0], ah[mi][1], ah[mi][2], ah[mi][3],
                         bb[nf >> 1][nf & 1], bb[nf >> 1][2 + (nf & 1)]);
                    HMMA(acc[mi][nf], al[mi][0], al[mi][1], al[mi][2], al[mi][3],
                         bb[nf >> 1][nf & 1], bb[nf >> 1][2 + (nf & 1)]);
                }
            // hi*lo
            #pragma unroll
            for (int nj = 0; nj < 4; ++nj)
                LDSM4(bb[nj][0], bb[nj][1], bb[nj][2], bb[nj][3], baddr[nj] + ko + 36864u);
            #pragma unroll
            for (int mi = 0; mi < 4; ++mi)
                #pragma unroll
                for (int nf = 0; nf < 8; ++nf)
                    HMMA(acc[mi][nf], ah[mi][0], ah[mi][1], ah[mi][2], ah[mi][3],
                         bb[nf >> 1][nf & 1], bb[nf >> 1][2 + (nf & 1)]);
        }
        __syncthreads();   // all warps done reading buffers -> safe to overwrite next iter
    }

    // ================= fold W from global into per-row partials =================
    float* redp = reinterpret_cast<float*>(sm + OFF_REDP);
    const float* wp = w + ((size_t)p << 16);
    #pragma unroll
    for (int mi = 0; mi < 4; ++mi)
        #pragma unroll
        for (int half = 0; half < 2; ++half) {
            int rl = warp_m * 64 + mi * 16 + (lane >> 2) + half * 8;
            const float* wr = wp + (size_t)(s0 + rl) * 256 + warp_n * 64 + (lane & 3) * 2;
            float part = 0.f;
            #pragma unroll
            for (int nf = 0; nf < 8; ++nf) {
                float2 wv = __ldg(reinterpret_cast<const float2*>(wr + nf * 8));
                part = fmaf(acc[mi][nf][half * 2 + 0], wv.x, part);
                part = fmaf(acc[mi][nf][half * 2 + 1], wv.y, part);
            }
            redp[rl * 17 + warp_n * 4 + (lane & 3)] = part;
        }

    // ================= per-row x sums from xsave (warp per 16 rows) =================
    float* xs   = reinterpret_cast<float*>(sm + OFF_XS);
    float* rssm = reinterpret_cast<float*>(sm + OFF_RS);
    float* s2sm = reinterpret_cast<float*>(sm + OFF_S2);
    #pragma unroll
    for (int j = 0; j < 16; ++j) {
        int r = wid * 16 + j;
        float4 v0 = *reinterpret_cast<const float4*>(xs + r * 256 + lane * 4);
        float4 v1 = *reinterpret_cast<const float4*>(xs + r * 256 + 128 + lane * 4);
        float rsv = v0.x + v0.y + v0.z + v0.w + v1.x + v1.y + v1.z + v1.w;
        float s2v = v0.x * v0.x + v0.y * v0.y + v0.z * v0.z + v0.w * v0.w
                  + v1.x * v1.x + v1.y * v1.y + v1.z * v1.z + v1.w * v1.w;
        #pragma unroll
        for (int o = 16; o; o >>= 1) {
            rsv += __shfl_xor_sync(0xffffffffu, rsv, o);
            s2v += __shfl_xor_sync(0xffffffffu, s2v, o);
        }
        if (lane == 0) { rssm[r] = rsv; s2sm[r] = s2v; }
    }
    __syncthreads();

    // ================= finalize red + BN partials =================
    float* redsm = reinterpret_cast<float*>(sm + OFF_RED);
    float vals[5] = {0.f, 0.f, 0.f, 0.f, 0.f};
    if (tid < 128) {
        float rsum = 0.f;
        #pragma unroll
        for (int l = 0; l < 16; ++l) rsum += redp[tid * 17 + l];
        float red = rsum * 0.0625f;    // 1/sqrt(256)
        redsm[tid] = red;
        float xr = rssm[tid], x2 = s2sm[tid];
        vals[0] = xr; vals[1] = x2; vals[2] = red; vals[3] = red * red; vals[4] = red * xr;
    }
    float* w8 = reinterpret_cast<float*>(sm + OFF_W8);
    float out5[5];
    #pragma unroll
    for (int q = 0; q < 5; ++q) {
        float v = vals[q];
        #pragma unroll
        for (int o = 16; o; o >>= 1) v += __shfl_xor_sync(0xffffffffu, v, o);
        if (lane == 0) w8[wid] = v;
        __syncthreads();
        if (tid == 0) {
            float r = 0.f;
            for (int t = 0; t < 8; ++t) r += w8[t];
            out5[q] = r;
        }
        __syncthreads();
    }

    // ================= cross-CTA BN handshake (16 CTAs per channel) =================
    float* bc = reinterpret_cast<float*>(sm + OFF_BC);
    if (tid == 0) {
        int slot = (p * 16 + bx) * 5;
        #pragma unroll
        for (int q = 0; q < 5; ++q) g_partials[slot + q] = out5[q];
        __threadfence();
        int o = atomicAdd(&g_cnt[p], 1);
        if (o == 15) {
            __threadfence();
            float sx = 0.f, sx2 = 0.f, sr = 0.f, sr2 = 0.f, cr = 0.f;
            for (int c = 0; c < 16; ++c) {
                const float* q = g_partials + (p * 16 + c) * 5;
                sx += q[0]; sx2 += q[1]; sr += q[2]; sr2 += q[3]; cr += q[4];
            }
            const float N = (float)(B_ * S_ * D_);
            float sumy  = sx + (float)D_ * sr;
            float sumy2 = sx2 + 2.f * cr + (float)D_ * sr2;
            float mean = sumy / N;
            float var  = sumy2 / N - mean * mean;
            float sc = __ldg(gamma + p) * rsqrtf(var + 1e-5f);
            g_scale[p] = sc;
            g_bias[p]  = __ldg(beta + p) - mean * sc;
            __threadfence();
            atomicExch(&g_flag[p], 1);
        }
        volatile int* fl = (volatile int*)&g_flag[p];
        while (*fl == 0) __nanosleep(64);
        __threadfence();
        bc[0] = g_scale[p];
        bc[1] = g_bias[p];
        int o2 = atomicAdd(&g_cnt2[p], 1);
        if (o2 == 15) {        // all 16 CTAs have consumed scale/bias: reset for next replay
            g_flag[p] = 0; g_cnt[p] = 0; g_cnt2[p] = 0;
        }
    }
    __syncthreads();
    const float sc = bc[0], bi = bc[1];

    // ================= output: out = (x + red) * sc + bi =================
    float* ob = out + ((size_t)(b * P_ + p) << 16) + (size_t)s0 * 256;
    #pragma unroll
    for (int j = 0; j < 16; ++j) {
        int r = wid * 16 + j;
        float red = redsm[r];
        #pragma unroll
        for (int it = 0; it < 2; ++it) {
            float4 v = *reinterpret_cast<const float4*>(xs + r * 256 + it * 128 + lane * 4);
            v.x = fmaf(v.x + red, sc, bi);
            v.y = fmaf(v.y + red, sc, bi);
            v.z = fmaf(v.z + red, sc, bi);
            v.w = fmaf(v.w + red, sc, bi);
            *reinterpret_cast<float4*>(ob + (size_t)r * 256 + it * 128 + lane * 4) = v;
        }
    }
}

// =====================================================================
extern "C" void kernel_launch(void* const* d_in, const int* in_sizes, int n_in,
                              void* d_out, int out_size)
{
    const float* x     = (const float*)d_in[0];
    const float* w     = (const float*)d_in[1];
    const float* gamma = (const float*)d_in[2];
    const float* beta  = (const float*)d_in[3];
    float* out = (float*)d_out;

    cudaFuncSetAttribute(da_fused_kernel,
                         cudaFuncAttributeMaxDynamicSharedMemorySize, SMEM_BYTES);

    dim3 grid(16, P_);   // blockIdx.x = b*2+st (channel CTAs contiguous), blockIdx.y = p
    da_fused_kernel<<<grid, 256, SMEM_BYTES>>>(x, w, gamma, beta, out);
}

// round 5
// speedup vs baseline: 1.0534x; 1.0534x over previous
#include <cuda_runtime.h>
#include <cuda_bf16.h>
#include <cstdint>

#define B_ 8
#define P_ 64
#define S_ 256
#define D_ 256

// ---------------- device scratch (zero-init at load; reset each run) ----------------
__device__ float g_partials[P_ * 16 * 5];
__device__ float g_scale[P_];
__device__ float g_bias[P_];
__device__ int   g_cnt[P_];
__device__ int   g_cnt2[P_];
__device__ int   g_flag[P_];

__device__ __forceinline__ uint32_t smem_to_u32(const void* p) {
    uint32_t a;
    asm("{ .reg .u64 t; cvta.to.shared.u64 t, %1; cvt.u32.u64 %0, t; }" : "=r"(a) : "l"(p));
    return a;
}

#define LDSM4(d0, d1, d2, d3, a) \
    asm volatile("ldmatrix.sync.aligned.m8n8.x4.shared.b16 {%0,%1,%2,%3}, [%4];" \
                 : "=r"(d0), "=r"(d1), "=r"(d2), "=r"(d3) : "r"(a))

#define HMMA(c, a0, a1, a2, a3, b0, b1) \
    asm volatile("mma.sync.aligned.m16n8k16.row.col.f32.bf16.bf16.f32 " \
                 "{%0,%1,%2,%3}, {%4,%5,%6,%7}, {%8,%9}, {%0,%1,%2,%3};" \
                 : "+f"((c)[0]), "+f"((c)[1]), "+f"((c)[2]), "+f"((c)[3]) \
                 : "r"(a0), "r"(a1), "r"(a2), "r"(a3), "r"(b0), "r"(b1))

// ---------------- smem layout (bytes) ----------------
constexpr int ROWB      = 144;                       // 64 k *2B + 16B pad (ldmatrix conflict-free)
constexpr int OFF_XS    = 0;                         // fp32 x rows [s0,s0+128): 128*1024 = 131072
constexpr int OFF_BH    = 131072;                    // hi bf16 chunk: 256*144 = 36864
constexpr int OFF_BL    = OFF_BH + 36864;            // lo bf16 chunk
constexpr int SMEM_BYTES = OFF_BL + 36864;           // 204800
// reuse of BH/BL after last mma:
constexpr int OFF_REDP  = OFF_BH;                    // 128*33*4 = 16896
constexpr int OFF_RS    = OFF_REDP + 16896;          // 512
constexpr int OFF_S2    = OFF_RS + 512;              // 512
constexpr int OFF_RED   = OFF_S2 + 512;              // 512
constexpr int OFF_W16   = OFF_RED + 512;             // 64
constexpr int OFF_BC    = OFF_W16 + 64;              // 8

// =====================================================================
__global__ void __launch_bounds__(512, 1)
da_fused_kernel(const float* __restrict__ x, const float* __restrict__ w,
                const float* __restrict__ gamma, const float* __restrict__ beta,
                float* __restrict__ out)
{
    extern __shared__ __align__(16) char sm[];
    const uint32_t smb = smem_to_u32(sm);
    const int tid = threadIdx.x, wid = tid >> 5, lane = tid & 31;
    const int bx = blockIdx.x;                 // 0..15 = b*2 + st
    const int b = bx >> 1, st = bx & 1;
    const int p = blockIdx.y;
    const int s0 = st * 128;
    const float* xbp = x + (size_t)(b * P_ + p) * (S_ * D_);

    const int warp_m = wid >> 3;   // 0..1 : 64 m-rows
    const int warp_n = wid & 7;    // 0..7 : 32 n-cols

    // accumulators: 4 m-frags x 4 n-frags x 4 f32 = 64 regs
    float acc[4][4][4];
    #pragma unroll
    for (int mi = 0; mi < 4; ++mi)
        #pragma unroll
        for (int nf = 0; nf < 4; ++nf)
            #pragma unroll
            for (int q = 0; q < 4; ++q) acc[mi][nf][q] = 0.f;

    // ldmatrix per-lane addressing
    const uint32_t lrow = lane & 15;
    const uint32_t lcol = (lane >> 4) * 16;
    uint32_t aaddr[4], baddr[2];
    #pragma unroll
    for (int mi = 0; mi < 4; ++mi)
        aaddr[mi] = smb + OFF_BH + (uint32_t)(s0 + warp_m * 64 + mi * 16 + lrow) * ROWB + lcol;
    #pragma unroll
    for (int nj = 0; nj < 2; ++nj)
        baddr[nj] = smb + OFF_BH + (uint32_t)(warp_n * 32 + nj * 16 + lrow) * ROWB + lcol;

    const int rbase = tid >> 4;    // 0..31
    const int c4    = tid & 15;    // float4 col in 64-k chunk

    // ================= k-chunk loop =================
    for (int kc = 0; kc < 4; ++kc) {
        __syncthreads();   // previous chunk's consumers done
        const float* xc = xbp + kc * 64 + c4 * 4;
        #pragma unroll
        for (int j = 0; j < 8; ++j) {
            int row = rbase + 32 * j;
            float4 v = __ldg(reinterpret_cast<const float4*>(xc + (size_t)row * D_));
            __nv_bfloat162 h01 = __floats2bfloat162_rn(v.x, v.y);
            __nv_bfloat162 h23 = __floats2bfloat162_rn(v.z, v.w);
            __nv_bfloat162 l01 = __floats2bfloat162_rn(v.x - __low2float(h01),
                                                       v.y - __high2float(h01));
            __nv_bfloat162 l23 = __floats2bfloat162_rn(v.z - __low2float(h23),
                                                       v.w - __high2float(h23));
            uint32_t off = (uint32_t)row * ROWB + (uint32_t)c4 * 8;
            *reinterpret_cast<uint2*>(sm + OFF_BH + off) =
                make_uint2(*reinterpret_cast<uint32_t*>(&h01), *reinterpret_cast<uint32_t*>(&h23));
            *reinterpret_cast<uint2*>(sm + OFF_BL + off) =
                make_uint2(*reinterpret_cast<uint32_t*>(&l01), *reinterpret_cast<uint32_t*>(&l23));
            int rl = row - s0;
            if (rl >= 0 && rl < 128)
                *reinterpret_cast<float4*>(sm + OFF_XS + (size_t)rl * 1024 + kc * 256 + c4 * 16) = v;
        }
        __syncthreads();

        #pragma unroll
        for (int ks = 0; ks < 4; ++ks) {
            const uint32_t ko = (uint32_t)ks * 32;
            uint32_t ah[4][4], al[4][4], bb[2][4];
            #pragma unroll
            for (int mi = 0; mi < 4; ++mi) {
                LDSM4(ah[mi][0], ah[mi][1], ah[mi][2], ah[mi][3], aaddr[mi] + ko);
                LDSM4(al[mi][0], al[mi][1], al[mi][2], al[mi][3], aaddr[mi] + ko + 36864u);
            }
            #pragma unroll
            for (int nj = 0; nj < 2; ++nj)
                LDSM4(bb[nj][0], bb[nj][1], bb[nj][2], bb[nj][3], baddr[nj] + ko);
            // hi*hi and lo*hi
            #pragma unroll
            for (int mi = 0; mi < 4; ++mi)
                #pragma unroll
                for (int nf = 0; nf < 4; ++nf) {
                    HMMA(acc[mi][nf], ah[mi][0], ah[mi][1], ah[mi][2], ah[mi][3],
                         bb[nf >> 1][nf & 1], bb[nf >> 1][2 + (nf & 1)]);
                    HMMA(acc[mi][nf], al[mi][0], al[mi][1], al[mi][2], al[mi][3],
                         bb[nf >> 1][nf & 1], bb[nf >> 1][2 + (nf & 1)]);
                }
            // hi*lo
            #pragma unroll
            for (int nj = 0; nj < 2; ++nj)
                LDSM4(bb[nj][0], bb[nj][1], bb[nj][2], bb[nj][3], baddr[nj] + ko + 36864u);
            #pragma unroll
            for (int mi = 0; mi < 4; ++mi)
                #pragma unroll
                for (int nf = 0; nf < 4; ++nf)
                    HMMA(acc[mi][nf], ah[mi][0], ah[mi][1], ah[mi][2], ah[mi][3],
                         bb[nf >> 1][nf & 1], bb[nf >> 1][2 + (nf & 1)]);
        }
    }

    __syncthreads();   // BH/BL reusable

    // ================= fold W from global into per-row partials =================
    float* redp = reinterpret_cast<float*>(sm + OFF_REDP);
    const float* wp = w + ((size_t)p << 16);
    #pragma unroll
    for (int mi = 0; mi < 4; ++mi)
        #pragma unroll
        for (int half = 0; half < 2; ++half) {
            int rl = warp_m * 64 + mi * 16 + (lane >> 2) + half * 8;
            const float* wr = wp + (size_t)(s0 + rl) * 256 + warp_n * 32 + (lane & 3) * 2;
            float part = 0.f;
            #pragma unroll
            for (int nf = 0; nf < 4; ++nf) {
                float2 wv = __ldg(reinterpret_cast<const float2*>(wr + nf * 8));
                part = fmaf(acc[mi][nf][half * 2 + 0], wv.x, part);
                part = fmaf(acc[mi][nf][half * 2 + 1], wv.y, part);
            }
            redp[rl * 33 + warp_n * 4 + (lane & 3)] = part;
        }

    // ================= per-row x sums from xsave (warp per 8 rows) =================
    float* xs   = reinterpret_cast<float*>(sm + OFF_XS);
    float* rssm = reinterpret_cast<float*>(sm + OFF_RS);
    float* s2sm = reinterpret_cast<float*>(sm + OFF_S2);
    #pragma unroll
    for (int j = 0; j < 8; ++j) {
        int r = wid * 8 + j;
        float4 v0 = *reinterpret_cast<const float4*>(xs + r * 256 + lane * 4);
        float4 v1 = *reinterpret_cast<const float4*>(xs + r * 256 + 128 + lane * 4);
        float rsv = v0.x + v0.y + v0.z + v0.w + v1.x + v1.y + v1.z + v1.w;
        float s2v = v0.x * v0.x + v0.y * v0.y + v0.z * v0.z + v0.w * v0.w
                  + v1.x * v1.x + v1.y * v1.y + v1.z * v1.z + v1.w * v1.w;
        #pragma unroll
        for (int o = 16; o; o >>= 1) {
            rsv += __shfl_xor_sync(0xffffffffu, rsv, o);
            s2v += __shfl_xor_sync(0xffffffffu, s2v, o);
        }
        if (lane == 0) { rssm[r] = rsv; s2sm[r] = s2v; }
    }
    __syncthreads();

    // ================= finalize red + BN partials =================
    float* redsm = reinterpret_cast<float*>(sm + OFF_RED);
    float vals[5] = {0.f, 0.f, 0.f, 0.f, 0.f};
    if (tid < 128) {
        float rsum = 0.f;
        #pragma unroll
        for (int l = 0; l < 32; ++l) rsum += redp[tid * 33 + l];
        float red = rsum * 0.0625f;    // 1/sqrt(256)
        redsm[tid] = red;
        float xr = rssm[tid], x2 = s2sm[tid];
        vals[0] = xr; vals[1] = x2; vals[2] = red; vals[3] = red * red; vals[4] = red * xr;
    }
    float* w16 = reinterpret_cast<float*>(sm + OFF_W16);
    float out5[5];
    #pragma unroll
    for (int q = 0; q < 5; ++q) {
        float v = vals[q];
        #pragma unroll
        for (int o = 16; o; o >>= 1) v += __shfl_xor_sync(0xffffffffu, v, o);
        if (lane == 0) w16[wid] = v;
        __syncthreads();
        if (tid == 0) {
            float r = 0.f;
            for (int t = 0; t < 16; ++t) r += w16[t];
            out5[q] = r;
        }
        __syncthreads();
    }

    // ================= cross-CTA BN handshake (16 CTAs per channel) =================
    float* bc = reinterpret_cast<float*>(sm + OFF_BC);
    if (tid == 0) {
        int slot = (p * 16 + bx) * 5;
        #pragma unroll
        for (int q = 0; q < 5; ++q) g_partials[slot + q] = out5[q];
        __threadfence();
        int o = atomicAdd(&g_cnt[p], 1);
        if (o == 15) {
            __threadfence();
            float sx = 0.f, sx2 = 0.f, sr = 0.f, sr2 = 0.f, cr = 0.f;
            for (int c = 0; c < 16; ++c) {
                const float* q = g_partials + (p * 16 + c) * 5;
                sx += q[0]; sx2 += q[1]; sr += q[2]; sr2 += q[3]; cr += q[4];
            }
            const float N = (float)(B_ * S_ * D_);
            float sumy  = sx + (float)D_ * sr;
            float sumy2 = sx2 + 2.f * cr + (float)D_ * sr2;
            float mean = sumy / N;
            float var  = sumy2 / N - mean * mean;
            float sc = __ldg(gamma + p) * rsqrtf(var + 1e-5f);
            g_scale[p] = sc;
            g_bias[p]  = __ldg(beta + p) - mean * sc;
            __threadfence();
            atomicExch(&g_flag[p], 1);
        }
        volatile int* fl = (volatile int*)&g_flag[p];
        while (*fl == 0) __nanosleep(64);
        __threadfence();
        bc[0] = g_scale[p];
        bc[1] = g_bias[p];
        int o2 = atomicAdd(&g_cnt2[p], 1);
        if (o2 == 15) {        // all consumers done: reset for next graph replay
            g_flag[p] = 0; g_cnt[p] = 0; g_cnt2[p] = 0;
        }
    }
    __syncthreads();
    const float sc = bc[0], bi = bc[1];

    // ================= output: out = (x + red) * sc + bi =================
    float* ob = out + ((size_t)(b * P_ + p) << 16) + (size_t)s0 * 256;
    #pragma unroll
    for (int j = 0; j < 8; ++j) {
        int r = wid * 8 + j;
        float red = redsm[r];
        #pragma unroll
        for (int it = 0; it < 2; ++it) {
            float4 v = *reinterpret_cast<const float4*>(xs + r * 256 + it * 128 + lane * 4);
            v.x = fmaf(v.x + red, sc, bi);
            v.y = fmaf(v.y + red, sc, bi);
            v.z = fmaf(v.z + red, sc, bi);
            v.w = fmaf(v.w + red, sc, bi);
            *reinterpret_cast<float4*>(ob + (size_t)r * 256 + it * 128 + lane * 4) = v;
        }
    }
}

// =====================================================================
extern "C" void kernel_launch(void* const* d_in, const int* in_sizes, int n_in,
                              void* d_out, int out_size)
{
    const float* x     = (const float*)d_in[0];
    const float* w     = (const float*)d_in[1];
    const float* gamma = (const float*)d_in[2];
    const float* beta  = (const float*)d_in[3];
    float* out = (float*)d_out;

    cudaFuncSetAttribute(da_fused_kernel,
                         cudaFuncAttributeMaxDynamicSharedMemorySize, SMEM_BYTES);

    dim3 grid(16, P_);   // blockIdx.x = b*2+st (channel CTAs contiguous), blockIdx.y = p
    da_fused_kernel<<<grid, 512, SMEM_BYTES>>>(x, w, gamma, beta, out);
}

// round 6
// speedup vs baseline: 1.1051x; 1.0492x over previous
#include <cuda_runtime.h>
#include <cuda_bf16.h>
#include <cstdint>

#define B_ 8
#define P_ 64
#define S_ 256
#define D_ 256

// ---------------- device scratch (zero-init at load; reset each run) ----------------
__device__ float g_partials[P_ * 16 * 5];
__device__ float g_scale[P_];
__device__ float g_bias[P_];
__device__ int   g_cnt[P_];
__device__ int   g_cnt2[P_];
__device__ int   g_flag[P_];

__device__ __forceinline__ uint32_t smem_to_u32(const void* p) {
    uint32_t a;
    asm("{ .reg .u64 t; cvta.to.shared.u64 t, %1; cvt.u32.u64 %0, t; }" : "=r"(a) : "l"(p));
    return a;
}

#define LDSM4(d0, d1, d2, d3, a) \
    asm volatile("ldmatrix.sync.aligned.m8n8.x4.shared.b16 {%0,%1,%2,%3}, [%4];" \
                 : "=r"(d0), "=r"(d1), "=r"(d2), "=r"(d3) : "r"(a))

#define HMMA(c, a0, a1, a2, a3, b0, b1) \
    asm volatile("mma.sync.aligned.m16n8k16.row.col.f32.bf16.bf16.f32 " \
                 "{%0,%1,%2,%3}, {%4,%5,%6,%7}, {%8,%9}, {%0,%1,%2,%3};" \
                 : "+f"((c)[0]), "+f"((c)[1]), "+f"((c)[2]), "+f"((c)[3]) \
                 : "r"(a0), "r"(a1), "r"(a2), "r"(a3), "r"(b0), "r"(b1))

// ---------------- smem layout (bytes) ----------------
constexpr int ROWB    = 80;                       // 32 k *2B + 16B pad (ldmatrix conflict-free)
constexpr int CHB     = 256 * ROWB;               // 20480 per hi or lo buffer
constexpr int OFF_XS  = 0;                        // fp32 x rows [s0,s0+128): 128*1024 = 131072
constexpr int OFF_B   = 131072;                   // [BH0][BL0][BH1][BL1] = 4*20480 = 81920
constexpr int SMEM_BYTES = OFF_B + 4 * CHB;       // 212992
// reuse of buffer region after last mma:
constexpr int OFF_REDP = OFF_B;                   // 128*33*4 = 16896
constexpr int OFF_RS   = OFF_REDP + 16896;        // 512
constexpr int OFF_S2   = OFF_RS + 512;            // 512
constexpr int OFF_RED  = OFF_S2 + 512;            // 512
constexpr int OFF_W16  = OFF_RED + 512;           // 64
constexpr int OFF_BC   = OFF_W16 + 64;            // 8

// =====================================================================
__global__ void __launch_bounds__(512, 1)
da_fused_kernel(const float* __restrict__ x, const float* __restrict__ w,
                const float* __restrict__ gamma, const float* __restrict__ beta,
                float* __restrict__ out)
{
    extern __shared__ __align__(16) char sm[];
    const uint32_t smb = smem_to_u32(sm);
    const int tid = threadIdx.x, wid = tid >> 5, lane = tid & 31;
    const int bx = blockIdx.x;                 // 0..15 = b*2 + st
    const int b = bx >> 1, st = bx & 1;
    const int p = blockIdx.y;
    const int s0 = st * 128;
    const float* xbp = x + (size_t)(b * P_ + p) * (S_ * D_);

    const int warp_m = wid >> 3;   // 0..1 : 64 m-rows
    const int warp_n = wid & 7;    // 0..7 : 32 n-cols

    // accumulators: 4 m-frags x 4 n-frags x 4 f32 = 64 regs
    float acc[4][4][4];
    #pragma unroll
    for (int mi = 0; mi < 4; ++mi)
        #pragma unroll
        for (int nf = 0; nf < 4; ++nf)
            #pragma unroll
            for (int q = 0; q < 4; ++q) acc[mi][nf][q] = 0.f;

    // ldmatrix per-lane addressing (buffer-0 base; +parity*2*CHB per chunk, +CHB for lo)
    const uint32_t lrow = lane & 15;
    const uint32_t lcol = (lane >> 4) * 16;
    uint32_t aaddr[4], baddr[2];
    #pragma unroll
    for (int mi = 0; mi < 4; ++mi)
        aaddr[mi] = smb + OFF_B + (uint32_t)(s0 + warp_m * 64 + mi * 16 + lrow) * ROWB + lcol;
    #pragma unroll
    for (int nj = 0; nj < 2; ++nj)
        baddr[nj] = smb + OFF_B + (uint32_t)(warp_n * 32 + nj * 16 + lrow) * ROWB + lcol;

    const int c4 = tid & 7;        // float4 col group within 32-k chunk
    const int rb = tid >> 3;       // 0..63 row base (4 rows per thread, stride 64)

    float4 pf[4];

    // ---- prefetch + convert chunk 0 into buffer 0 ----
    {
        const float* xc = xbp + c4 * 4;
        #pragma unroll
        for (int j = 0; j < 4; ++j)
            pf[j] = __ldg(reinterpret_cast<const float4*>(xc + (size_t)(rb + 64 * j) * D_));
        #pragma unroll
        for (int j = 0; j < 4; ++j) {
            int row = rb + 64 * j;
            float4 v = pf[j];
            __nv_bfloat162 h01 = __floats2bfloat162_rn(v.x, v.y);
            __nv_bfloat162 h23 = __floats2bfloat162_rn(v.z, v.w);
            __nv_bfloat162 l01 = __floats2bfloat162_rn(v.x - __low2float(h01),
                                                       v.y - __high2float(h01));
            __nv_bfloat162 l23 = __floats2bfloat162_rn(v.z - __low2float(h23),
                                                       v.w - __high2float(h23));
            uint32_t off = (uint32_t)row * ROWB + (uint32_t)c4 * 8;
            *reinterpret_cast<uint2*>(sm + OFF_B + off) =
                make_uint2(*reinterpret_cast<uint32_t*>(&h01), *reinterpret_cast<uint32_t*>(&h23));
            *reinterpret_cast<uint2*>(sm + OFF_B + CHB + off) =
                make_uint2(*reinterpret_cast<uint32_t*>(&l01), *reinterpret_cast<uint32_t*>(&l23));
            int rl = row - s0;
            if (rl >= 0 && rl < 128)
                *reinterpret_cast<float4*>(sm + OFF_XS + (size_t)rl * 1024 + c4 * 16) = v;
        }
    }
    __syncthreads();

    // ================= pipelined k-chunk loop (8 chunks of K=32) =================
    for (int kc = 0; kc < 8; ++kc) {
        // ---- issue next-chunk LDGs first (latency hidden by MMA below) ----
        if (kc < 7) {
            const float* xn = xbp + (kc + 1) * 32 + c4 * 4;
            #pragma unroll
            for (int j = 0; j < 4; ++j)
                pf[j] = __ldg(reinterpret_cast<const float4*>(xn + (size_t)(rb + 64 * j) * D_));
        }

        // ---- MMA on buffer[kc&1] ----
        const uint32_t bufo = (uint32_t)(kc & 1) * (2 * CHB);
        #pragma unroll
        for (int ks = 0; ks < 2; ++ks) {
            const uint32_t ko = bufo + (uint32_t)ks * 32;
            uint32_t bh[2][4], bl[2][4];
            #pragma unroll
            for (int nj = 0; nj < 2; ++nj) {
                LDSM4(bh[nj][0], bh[nj][1], bh[nj][2], bh[nj][3], baddr[nj] + ko);
                LDSM4(bl[nj][0], bl[nj][1], bl[nj][2], bl[nj][3], baddr[nj] + ko + CHB);
            }
            #pragma unroll
            for (int mi = 0; mi < 4; ++mi) {
                uint32_t ah[4], al[4];
                LDSM4(ah[0], ah[1], ah[2], ah[3], aaddr[mi] + ko);
                LDSM4(al[0], al[1], al[2], al[3], aaddr[mi] + ko + CHB);
                #pragma unroll
                for (int nf = 0; nf < 4; ++nf) {
                    const int nj = nf >> 1, nk = nf & 1;
                    HMMA(acc[mi][nf], ah[0], ah[1], ah[2], ah[3],
                         bh[nj][nk], bh[nj][2 + nk]);             // hi*hi
                    HMMA(acc[mi][nf], al[0], al[1], al[2], al[3],
                         bh[nj][nk], bh[nj][2 + nk]);             // lo*hi
                    HMMA(acc[mi][nf], ah[0], ah[1], ah[2], ah[3],
                         bl[nj][nk], bl[nj][2 + nk]);             // hi*lo
                }
            }
        }

        // ---- convert prefetched chunk kc+1 into the other buffer ----
        if (kc < 7) {
            char* bhp = sm + OFF_B + (size_t)((kc + 1) & 1) * (2 * CHB);
            #pragma unroll
            for (int j = 0; j < 4; ++j) {
                int row = rb + 64 * j;
                float4 v = pf[j];
                __nv_bfloat162 h01 = __floats2bfloat162_rn(v.x, v.y);
                __nv_bfloat162 h23 = __floats2bfloat162_rn(v.z, v.w);
                __nv_bfloat162 l01 = __floats2bfloat162_rn(v.x - __low2float(h01),
                                                           v.y - __high2float(h01));
                __nv_bfloat162 l23 = __floats2bfloat162_rn(v.z - __low2float(h23),
                                                           v.w - __high2float(h23));
                uint32_t off = (uint32_t)row * ROWB + (uint32_t)c4 * 8;
                *reinterpret_cast<uint2*>(bhp + off) =
                    make_uint2(*reinterpret_cast<uint32_t*>(&h01), *reinterpret_cast<uint32_t*>(&h23));
                *reinterpret_cast<uint2*>(bhp + CHB + off) =
                    make_uint2(*reinterpret_cast<uint32_t*>(&l01), *reinterpret_cast<uint32_t*>(&l23));
                int rl = row - s0;
                if (rl >= 0 && rl < 128)
                    *reinterpret_cast<float4*>(sm + OFF_XS + (size_t)rl * 1024 +
                                               (kc + 1) * 128 + c4 * 16) = v;
            }
        }
        __syncthreads();
    }

    // ================= fold W from global into per-row partials =================
    float* redp = reinterpret_cast<float*>(sm + OFF_REDP);
    const float* wp = w + ((size_t)p << 16);
    #pragma unroll
    for (int mi = 0; mi < 4; ++mi)
        #pragma unroll
        for (int half = 0; half < 2; ++half) {
            int rl = warp_m * 64 + mi * 16 + (lane >> 2) + half * 8;
            const float* wr = wp + (size_t)(s0 + rl) * 256 + warp_n * 32 + (lane & 3) * 2;
            float part = 0.f;
            #pragma unroll
            for (int nf = 0; nf < 4; ++nf) {
                float2 wv = __ldg(reinterpret_cast<const float2*>(wr + nf * 8));
                part = fmaf(acc[mi][nf][half * 2 + 0], wv.x, part);
                part = fmaf(acc[mi][nf][half * 2 + 1], wv.y, part);
            }
            redp[rl * 33 + warp_n * 4 + (lane & 3)] = part;
        }

    // ================= per-row x sums from xsave (warp per 8 rows) =================
    float* xs   = reinterpret_cast<float*>(sm + OFF_XS);
    float* rssm = reinterpret_cast<float*>(sm + OFF_RS);
    float* s2sm = reinterpret_cast<float*>(sm + OFF_S2);
    #pragma unroll
    for (int j = 0; j < 8; ++j) {
        int r = wid * 8 + j;
        float4 v0 = *reinterpret_cast<const float4*>(xs + r * 256 + lane * 4);
        float4 v1 = *reinterpret_cast<const float4*>(xs + r * 256 + 128 + lane * 4);
        float rsv = v0.x + v0.y + v0.z + v0.w + v1.x + v1.y + v1.z + v1.w;
        float s2v = v0.x * v0.x + v0.y * v0.y + v0.z * v0.z + v0.w * v0.w
                  + v1.x * v1.x + v1.y * v1.y + v1.z * v1.z + v1.w * v1.w;
        #pragma unroll
        for (int o = 16; o; o >>= 1) {
            rsv += __shfl_xor_sync(0xffffffffu, rsv, o);
            s2v += __shfl_xor_sync(0xffffffffu, s2v, o);
        }
        if (lane == 0) { rssm[r] = rsv; s2sm[r] = s2v; }
    }
    __syncthreads();

    // ================= finalize red + BN partials =================
    float* redsm = reinterpret_cast<float*>(sm + OFF_RED);
    float vals[5] = {0.f, 0.f, 0.f, 0.f, 0.f};
    if (tid < 128) {
        float rsum = 0.f;
        #pragma unroll
        for (int l = 0; l < 32; ++l) rsum += redp[tid * 33 + l];
        float red = rsum * 0.0625f;    // 1/sqrt(256)
        redsm[tid] = red;
        float xr = rssm[tid], x2 = s2sm[tid];
        vals[0] = xr; vals[1] = x2; vals[2] = red; vals[3] = red * red; vals[4] = red * xr;
    }
    float* w16 = reinterpret_cast<float*>(sm + OFF_W16);
    float out5[5];
    #pragma unroll
    for (int q = 0; q < 5; ++q) {
        float v = vals[q];
        #pragma unroll
        for (int o = 16; o; o >>= 1) v += __shfl_xor_sync(0xffffffffu, v, o);
        if (lane == 0) w16[wid] = v;
        __syncthreads();
        if (tid == 0) {
            float r = 0.f;
            for (int t = 0; t < 16; ++t) r += w16[t];
            out5[q] = r;
        }
        __syncthreads();
    }

    // ================= cross-CTA BN handshake (16 CTAs per channel) =================
    float* bc = reinterpret_cast<float*>(sm + OFF_BC);
    if (tid == 0) {
        int slot = (p * 16 + bx) * 5;
        #pragma unroll
        for (int q = 0; q < 5; ++q) g_partials[slot + q] = out5[q];
        __threadfence();
        int o = atomicAdd(&g_cnt[p], 1);
        if (o == 15) {
            __threadfence();
            float sx = 0.f, sx2 = 0.f, sr = 0.f, sr2 = 0.f, cr = 0.f;
            for (int c = 0; c < 16; ++c) {
                const float* q = g_partials + (p * 16 + c) * 5;
                sx += q[0]; sx2 += q[1]; sr += q[2]; sr2 += q[3]; cr += q[4];
            }
            const float N = (float)(B_ * S_ * D_);
            float sumy  = sx + (float)D_ * sr;
            float sumy2 = sx2 + 2.f * cr + (float)D_ * sr2;
            float mean = sumy / N;
            float var  = sumy2 / N - mean * mean;
            float sc = __ldg(gamma + p) * rsqrtf(var + 1e-5f);
            g_scale[p] = sc;
            g_bias[p]  = __ldg(beta + p) - mean * sc;
            __threadfence();
            atomicExch(&g_flag[p], 1);
        }
        volatile int* fl = (volatile int*)&g_flag[p];
        while (*fl == 0) __nanosleep(64);
        __threadfence();
        bc[0] = g_scale[p];
        bc[1] = g_bias[p];
        int o2 = atomicAdd(&g_cnt2[p], 1);
        if (o2 == 15) {        // all consumers done: reset for next graph replay
            g_flag[p] = 0; g_cnt[p] = 0; g_cnt2[p] = 0;
        }
    }
    __syncthreads();
    const float sc = bc[0], bi = bc[1];

    // ================= output: out = (x + red) * sc + bi =================
    float* ob = out + ((size_t)(b * P_ + p) << 16) + (size_t)s0 * 256;
    #pragma unroll
    for (int j = 0; j < 8; ++j) {
        int r = wid * 8 + j;
        float red = redsm[r];
        #pragma unroll
        for (int it = 0; it < 2; ++it) {
            float4 v = *reinterpret_cast<const float4*>(xs + r * 256 + it * 128 + lane * 4);
            v.x = fmaf(v.x + red, sc, bi);
            v.y = fmaf(v.y + red, sc, bi);
            v.z = fmaf(v.z + red, sc, bi);
            v.w = fmaf(v.w + red, sc, bi);
            *reinterpret_cast<float4*>(ob + (size_t)r * 256 + it * 128 + lane * 4) = v;
        }
    }
}

// =====================================================================
extern "C" void kernel_launch(void* const* d_in, const int* in_sizes, int n_in,
                              void* d_out, int out_size)
{
    const float* x     = (const float*)d_in[0];
    const float* w     = (const float*)d_in[1];
    const float* gamma = (const float*)d_in[2];
    const float* beta  = (const float*)d_in[3];
    float* out = (float*)d_out;

    cudaFuncSetAttribute(da_fused_kernel,
                         cudaFuncAttributeMaxDynamicSharedMemorySize, SMEM_BYTES);

    dim3 grid(16, P_);   // blockIdx.x = b*2+st (channel CTAs contiguous), blockIdx.y = p
    da_fused_kernel<<<grid, 512, SMEM_BYTES>>>(x, w, gamma, beta, out);
}

// round 7
// speedup vs baseline: 1.3475x; 1.2193x over previous
#include <cuda_runtime.h>
#include <cuda_bf16.h>
#include <cstdint>

#define B_ 8
#define P_ 64
#define S_ 256
#define D_ 256

// ---------------- device scratch (zero-init at load; reset each run) ----------------
__device__ float g_partials[P_ * 32 * 5];
__device__ float g_scale[P_];
__device__ float g_bias[P_];
__device__ int   g_cnt[P_];
__device__ int   g_cnt2[P_];
__device__ int   g_flag[P_];

__device__ __forceinline__ uint32_t smem_to_u32(const void* p) {
    uint32_t a;
    asm("{ .reg .u64 t; cvta.to.shared.u64 t, %1; cvt.u32.u64 %0, t; }" : "=r"(a) : "l"(p));
    return a;
}

#define LDSM4(d0, d1, d2, d3, a) \
    asm volatile("ldmatrix.sync.aligned.m8n8.x4.shared.b16 {%0,%1,%2,%3}, [%4];" \
                 : "=r"(d0), "=r"(d1), "=r"(d2), "=r"(d3) : "r"(a))

#define HMMA(c, a0, a1, a2, a3, b0, b1) \
    asm volatile("mma.sync.aligned.m16n8k16.row.col.f32.bf16.bf16.f32 " \
                 "{%0,%1,%2,%3}, {%4,%5,%6,%7}, {%8,%9}, {%0,%1,%2,%3};" \
                 : "+f"((c)[0]), "+f"((c)[1]), "+f"((c)[2]), "+f"((c)[3]) \
                 : "r"(a0), "r"(a1), "r"(a2), "r"(a3), "r"(b0), "r"(b1))

// ---------------- smem layout (bytes) ----------------
constexpr int ROWB    = 144;                  // 64 k *2B + 16B pad (ldmatrix conflict-free)
constexpr int OFF_BH  = 0;                    // hi: 256*144 = 36864
constexpr int OFF_BL  = 36864;                // lo: 36864
constexpr int SMEM_BYTES = 73728;             // 72KB -> 2 CTAs/SM
// epilogue overlay (BH/BL dead after last MMA):
constexpr int OFF_XSE  = 0;                   // 64*256*4 = 65536
constexpr int OFF_REDP = 65536;               // 64*17*4 = 4352
constexpr int OFF_RS   = OFF_REDP + 4352;     // 256
constexpr int OFF_S2   = OFF_RS + 256;        // 256
constexpr int OFF_RED  = OFF_S2 + 256;        // 256
constexpr int OFF_W8   = OFF_RED + 256;       // 32
constexpr int OFF_BC   = OFF_W8 + 32;         // 8   (total 70696 <= 73728)

// =====================================================================
// CTA = (b, p, q): rows [q*64, q*64+64), all 256 t-cols. 256 thr, 2 CTA/SM.
// =====================================================================
__global__ void __launch_bounds__(256, 2)
da_fused_kernel(const float* __restrict__ x, const float* __restrict__ w,
                const float* __restrict__ gamma, const float* __restrict__ beta,
                float* __restrict__ out)
{
    extern __shared__ __align__(16) char sm[];
    const uint32_t smb = smem_to_u32(sm);
    const int tid = threadIdx.x, wid = tid >> 5, lane = tid & 31;
    const int bx = blockIdx.x;                 // 0..31 = b*4 + q
    const int b = bx >> 2, q = bx & 3;
    const int p = blockIdx.y;
    const int m0 = q * 64;                     // global row base of this CTA
    const float* xbp = x + (size_t)(b * P_ + p) * (S_ * D_);

    const int warp_m = wid >> 2;   // 0..1 : 32 m-rows
    const int warp_n = wid & 3;    // 0..3 : 64 n-cols

    // accumulators: 2 m-frags x 8 n-frags x 4 = 64 regs
    float acc[2][8][4];
    #pragma unroll
    for (int mi = 0; mi < 2; ++mi)
        #pragma unroll
        for (int nf = 0; nf < 8; ++nf)
            #pragma unroll
            for (int qq = 0; qq < 4; ++qq) acc[mi][nf][qq] = 0.f;

    // ldmatrix per-lane addressing (A reads the shared B tile at row offset m0)
    const uint32_t lrow = lane & 15;
    const uint32_t lcol = (lane >> 4) * 16;
    uint32_t aaddr[2], baddr[4];
    #pragma unroll
    for (int mi = 0; mi < 2; ++mi)
        aaddr[mi] = smb + OFF_BH + (uint32_t)(m0 + warp_m * 32 + mi * 16 + lrow) * ROWB + lcol;
    #pragma unroll
    for (int nj = 0; nj < 4; ++nj)
        baddr[nj] = smb + OFF_BH + (uint32_t)(warp_n * 64 + nj * 16 + lrow) * ROWB + lcol;

    const int rbase = tid >> 4;    // 0..15
    const int c4    = tid & 15;    // float4 col in 64-k chunk

    // ================= k-chunk loop (4 chunks of K=64) =================
    for (int kc = 0; kc < 4; ++kc) {
        __syncthreads();   // previous chunk's consumers done
        const float* xc = xbp + kc * 64 + c4 * 4;
        // two half-batches of 8 LDGs to keep MLP high and register peak low
        #pragma unroll
        for (int h = 0; h < 2; ++h) {
            float4 pv[8];
            #pragma unroll
            for (int j = 0; j < 8; ++j)
                pv[j] = __ldg(reinterpret_cast<const float4*>(
                    xc + (size_t)(rbase + 16 * (h * 8 + j)) * D_));
            #pragma unroll
            for (int j = 0; j < 8; ++j) {
                int row = rbase + 16 * (h * 8 + j);
                float4 v = pv[j];
                __nv_bfloat162 h01 = __floats2bfloat162_rn(v.x, v.y);
                __nv_bfloat162 h23 = __floats2bfloat162_rn(v.z, v.w);
                __nv_bfloat162 l01 = __floats2bfloat162_rn(v.x - __low2float(h01),
                                                           v.y - __high2float(h01));
                __nv_bfloat162 l23 = __floats2bfloat162_rn(v.z - __low2float(h23),
                                                           v.w - __high2float(h23));
                uint32_t off = (uint32_t)row * ROWB + (uint32_t)c4 * 8;
                *reinterpret_cast<uint2*>(sm + OFF_BH + off) =
                    make_uint2(*reinterpret_cast<uint32_t*>(&h01), *reinterpret_cast<uint32_t*>(&h23));
                *reinterpret_cast<uint2*>(sm + OFF_BL + off) =
                    make_uint2(*reinterpret_cast<uint32_t*>(&l01), *reinterpret_cast<uint32_t*>(&l23));
            }
        }
        __syncthreads();

        #pragma unroll
        for (int ks = 0; ks < 4; ++ks) {
            const uint32_t ko = (uint32_t)ks * 32;
            uint32_t ah[2][4], al[2][4];
            #pragma unroll
            for (int mi = 0; mi < 2; ++mi) {
                LDSM4(ah[mi][0], ah[mi][1], ah[mi][2], ah[mi][3], aaddr[mi] + ko);
                LDSM4(al[mi][0], al[mi][1], al[mi][2], al[mi][3], aaddr[mi] + ko + 36864u);
            }
            #pragma unroll
            for (int nj = 0; nj < 4; ++nj) {
                uint32_t bh[4], bl[4];
                LDSM4(bh[0], bh[1], bh[2], bh[3], baddr[nj] + ko);
                LDSM4(bl[0], bl[1], bl[2], bl[3], baddr[nj] + ko + 36864u);
                #pragma unroll
                for (int nk = 0; nk < 2; ++nk) {
                    const int nf = nj * 2 + nk;
                    #pragma unroll
                    for (int mi = 0; mi < 2; ++mi) {
                        HMMA(acc[mi][nf], ah[mi][0], ah[mi][1], ah[mi][2], ah[mi][3],
                             bh[nk], bh[2 + nk]);                          // hi*hi
                        HMMA(acc[mi][nf], al[mi][0], al[mi][1], al[mi][2], al[mi][3],
                             bh[nk], bh[2 + nk]);                          // lo*hi
                        HMMA(acc[mi][nf], ah[mi][0], ah[mi][1], ah[mi][2], ah[mi][3],
                             bl[nk], bl[2 + nk]);                          // hi*lo
                    }
                }
            }
        }
    }
    __syncthreads();   // BH/BL dead -> overlay region usable

    // ================= fold W into per-row partials =================
    float* redp = reinterpret_cast<float*>(sm + OFF_REDP);
    const float* wp = w + ((size_t)p << 16);
    #pragma unroll
    for (int mi = 0; mi < 2; ++mi)
        #pragma unroll
        for (int half = 0; half < 2; ++half) {
            int rl = warp_m * 32 + mi * 16 + (lane >> 2) + half * 8;   // 0..63 local
            const float* wr = wp + (size_t)(m0 + rl) * 256 + warp_n * 64 + (lane & 3) * 2;
            float part = 0.f;
            #pragma unroll
            for (int nf = 0; nf < 8; ++nf) {
                float2 wv = __ldg(reinterpret_cast<const float2*>(wr + nf * 8));
                part = fmaf(acc[mi][nf][half * 2 + 0], wv.x, part);
                part = fmaf(acc[mi][nf][half * 2 + 1], wv.y, part);
            }
            redp[rl * 17 + warp_n * 4 + (lane & 3)] = part;
        }

    // ================= re-read own x rows into smem + row sums =================
    float* xs   = reinterpret_cast<float*>(sm + OFF_XSE);
    float* rssm = reinterpret_cast<float*>(sm + OFF_RS);
    float* s2sm = reinterpret_cast<float*>(sm + OFF_S2);
    #pragma unroll
    for (int j = 0; j < 8; ++j) {
        int r = wid * 8 + j;                       // 0..63 local
        const float* xr = xbp + (size_t)(m0 + r) * 256;
        float4 v0 = __ldg(reinterpret_cast<const float4*>(xr + lane * 4));
        float4 v1 = __ldg(reinterpret_cast<const float4*>(xr + 128 + lane * 4));
        *reinterpret_cast<float4*>(xs + r * 256 + lane * 4) = v0;
        *reinterpret_cast<float4*>(xs + r * 256 + 128 + lane * 4) = v1;
        float rsv = v0.x + v0.y + v0.z + v0.w + v1.x + v1.y + v1.z + v1.w;
        float s2v = v0.x * v0.x + v0.y * v0.y + v0.z * v0.z + v0.w * v0.w
                  + v1.x * v1.x + v1.y * v1.y + v1.z * v1.z + v1.w * v1.w;
        #pragma unroll
        for (int o = 16; o; o >>= 1) {
            rsv += __shfl_xor_sync(0xffffffffu, rsv, o);
            s2v += __shfl_xor_sync(0xffffffffu, s2v, o);
        }
        if (lane == 0) { rssm[r] = rsv; s2sm[r] = s2v; }
    }
    __syncthreads();

    // ================= finalize red + BN partials =================
    float* redsm = reinterpret_cast<float*>(sm + OFF_RED);
    float vals[5] = {0.f, 0.f, 0.f, 0.f, 0.f};
    if (tid < 64) {
        float rsum = 0.f;
        #pragma unroll
        for (int l = 0; l < 16; ++l) rsum += redp[tid * 17 + l];
        float red = rsum * 0.0625f;    // 1/sqrt(256)
        redsm[tid] = red;
        float xr = rssm[tid], x2 = s2sm[tid];
        vals[0] = xr; vals[1] = x2; vals[2] = red; vals[3] = red * red; vals[4] = red * xr;
    }
    float* w8 = reinterpret_cast<float*>(sm + OFF_W8);
    float out5[5];
    #pragma unroll
    for (int qq = 0; qq < 5; ++qq) {
        float v = vals[qq];
        #pragma unroll
        for (int o = 16; o; o >>= 1) v += __shfl_xor_sync(0xffffffffu, v, o);
        if (lane == 0) w8[wid] = v;
        __syncthreads();
        if (tid == 0) {
            float r = 0.f;
            for (int t = 0; t < 8; ++t) r += w8[t];
            out5[qq] = r;
        }
        __syncthreads();
    }

    // ================= cross-CTA BN handshake (32 CTAs per channel) =================
    float* bc = reinterpret_cast<float*>(sm + OFF_BC);
    if (tid == 0) {
        int slot = (p * 32 + bx) * 5;
        #pragma unroll
        for (int qq = 0; qq < 5; ++qq) g_partials[slot + qq] = out5[qq];
        __threadfence();
        int o = atomicAdd(&g_cnt[p], 1);
        if (o == 31) {
            __threadfence();
            float sx = 0.f, sx2 = 0.f, sr = 0.f, sr2 = 0.f, cr = 0.f;
            for (int c = 0; c < 32; ++c) {
                const float* qp = g_partials + (p * 32 + c) * 5;
                sx += qp[0]; sx2 += qp[1]; sr += qp[2]; sr2 += qp[3]; cr += qp[4];
            }
            const float N = (float)(B_ * S_ * D_);
            float sumy  = sx + (float)D_ * sr;
            float sumy2 = sx2 + 2.f * cr + (float)D_ * sr2;
            float mean = sumy / N;
            float var  = sumy2 / N - mean * mean;
            float sc = __ldg(gamma + p) * rsqrtf(var + 1e-5f);
            g_scale[p] = sc;
            g_bias[p]  = __ldg(beta + p) - mean * sc;
            __threadfence();
            atomicExch(&g_flag[p], 1);
        }
        volatile int* fl = (volatile int*)&g_flag[p];
        while (*fl == 0) __nanosleep(64);
        __threadfence();
        bc[0] = g_scale[p];
        bc[1] = g_bias[p];
        int o2 = atomicAdd(&g_cnt2[p], 1);
        if (o2 == 31) {        // all consumers done: reset for next graph replay
            g_flag[p] = 0; g_cnt[p] = 0; g_cnt2[p] = 0;
        }
    }
    __syncthreads();
    const float sc = bc[0], bi = bc[1];

    // ================= output: out = (x + red) * sc + bi =================
    float* ob = out + ((size_t)(b * P_ + p) << 16) + (size_t)m0 * 256;
    #pragma unroll
    for (int j = 0; j < 8; ++j) {
        int r = wid * 8 + j;
        float red = redsm[r];
        #pragma unroll
        for (int it = 0; it < 2; ++it) {
            float4 v = *reinterpret_cast<const float4*>(xs + r * 256 + it * 128 + lane * 4);
            v.x = fmaf(v.x + red, sc, bi);
            v.y = fmaf(v.y + red, sc, bi);
            v.z = fmaf(v.z + red, sc, bi);
            v.w = fmaf(v.w + red, sc, bi);
            *reinterpret_cast<float4*>(ob + (size_t)r * 256 + it * 128 + lane * 4) = v;
        }
    }
}

// =====================================================================
extern "C" void kernel_launch(void* const* d_in, const int* in_sizes, int n_in,
                              void* d_out, int out_size)
{
    const float* x     = (const float*)d_in[0];
    const float* w     = (const float*)d_in[1];
    const float* gamma = (const float*)d_in[2];
    const float* beta  = (const float*)d_in[3];
    float* out = (float*)d_out;

    cudaFuncSetAttribute(da_fused_kernel,
                         cudaFuncAttributeMaxDynamicSharedMemorySize, SMEM_BYTES);

    dim3 grid(32, P_);   // blockIdx.x = b*4+q (channel CTAs contiguous), blockIdx.y = p
    da_fused_kernel<<<grid, 256, SMEM_BYTES>>>(x, w, gamma, beta, out);
}